// round 12
// baseline (speedup 1.0000x reference)
#include <cuda_runtime.h>
#include <cuda_bf16.h>
#include <cuda_fp16.h>
#include <cstdint>
#include <cstddef>

#define BB 4
#define CC 512
#define LL 2048
#define HH 8
#define DH 64
#define BL (BB*LL)

// ---------------------------------------------------------------------------
// Scratch (all single fp16)
// ---------------------------------------------------------------------------
__device__ __half g_xq[BL*CC];     // (B,L,C) transposed inputs
__device__ __half g_xk[BL*CC];
__device__ __half g_xv[BL*CC];
__device__ __half g_wq[CC*CC];
__device__ __half g_wk[CC*CC];
__device__ __half g_wv[CC*CC];
__device__ __half g_wo[CC*CC];
__device__ __half g_qhH[BL*CC];    // (B,L,C)
__device__ __half g_khH[BL*CC];    // (B,L,C)
__device__ __half g_vhH[BL*CC];    // (B,C,L)
__device__ __half g_ct[BL*CC];     // (B,L,C)

// ---------------------------------------------------------------------------
// Helpers
// ---------------------------------------------------------------------------
__device__ __forceinline__ uint32_t smem_u32(const void* p) {
    uint32_t a;
    asm("{ .reg .u64 t; cvta.to.shared.u64 t, %1; cvt.u32.u64 %0, t; }" : "=r"(a) : "l"(p));
    return a;
}

#define LDSM4(R, a) \
    asm volatile("ldmatrix.sync.aligned.m8n8.x4.shared.b16 {%0,%1,%2,%3}, [%4];" \
        : "=r"((R)[0]), "=r"((R)[1]), "=r"((R)[2]), "=r"((R)[3]) : "r"(a))

#define CPA16(d, s) \
    asm volatile("cp.async.cg.shared.global [%0], [%1], 16;" :: "r"(d), "l"(s))
#define CPC()   asm volatile("cp.async.commit_group;" ::: "memory")
#define CPW2()  asm volatile("cp.async.wait_group 2;" ::: "memory")
#define CPWALL() asm volatile("cp.async.wait_group 0;" ::: "memory")

__device__ __forceinline__ void mma_f16(float* c, const uint32_t* a, const uint32_t* b) {
    asm volatile("mma.sync.aligned.m16n8k16.row.col.f32.f16.f16.f32 "
        "{%0,%1,%2,%3}, {%4,%5,%6,%7}, {%8,%9}, {%0,%1,%2,%3};"
        : "+f"(c[0]), "+f"(c[1]), "+f"(c[2]), "+f"(c[3])
        : "r"(a[0]), "r"(a[1]), "r"(a[2]), "r"(a[3]), "r"(b[0]), "r"(b[1]));
}

__device__ __forceinline__ uint32_t packh2(float a, float b) {
    __half2 t = __floats2half2_rn(a, b);
    return *reinterpret_cast<uint32_t*>(&t);
}

// ---------------------------------------------------------------------------
// Pre-pass: transpose (B,C,L) fp32 -> (B*L, C) fp16, all 3 tensors in one grid
// ---------------------------------------------------------------------------
__global__ __launch_bounds__(256) void tconv_kernel(
    const float* __restrict__ Xq, const float* __restrict__ Xk, const float* __restrict__ Xv,
    __half* __restrict__ Tq, __half* __restrict__ Tk, __half* __restrict__ Tv)
{
    __shared__ float t[32][33];
    const int zz = blockIdx.z;
    const int which = zz >> 2, b = zz & 3;
    const float* X = (which == 0) ? Xq : (which == 1) ? Xk : Xv;
    __half* T = (which == 0) ? Tq : (which == 1) ? Tk : Tv;
    const int l0 = blockIdx.x * 32, c0 = blockIdx.y * 32;
    const int tx = threadIdx.x, ty = threadIdx.y;
    const float* Xb = X + ((size_t)b * CC + c0) * LL + l0;
#pragma unroll
    for (int i = 0; i < 4; i++)
        t[ty + i * 8][tx] = Xb[(size_t)(ty + i * 8) * LL + tx];
    __syncthreads();
    const size_t ob = ((size_t)b * LL + l0) * CC + c0;
#pragma unroll
    for (int i = 0; i < 4; i++) {
        int lr = ty + i * 8;
        T[ob + (size_t)lr * CC + tx] = __float2half_rn(t[tx][lr]);
    }
}

// All 4 weight matrices in one launch
__global__ __launch_bounds__(256) void wconv_kernel(
    const float* __restrict__ W0, const float* __restrict__ W1,
    const float* __restrict__ W2, const float* __restrict__ W3,
    __half* __restrict__ O0, __half* __restrict__ O1,
    __half* __restrict__ O2, __half* __restrict__ O3)
{
    int gi = blockIdx.x * 256 + threadIdx.x;
    int which = gi >> 18;           // CC*CC = 262144 = 2^18
    int i = gi & 0x3FFFF;
    const float* W = (which == 0) ? W0 : (which == 1) ? W1 : (which == 2) ? W2 : W3;
    __half* O = (which == 0) ? O0 : (which == 1) ? O1 : (which == 2) ? O2 : O3;
    O[i] = __float2half_rn(W[i]);
}

// ---------------------------------------------------------------------------
// GEMM: D[m,n] = sum_k A[m,k]*B[n,k] (+bias), single-pass fp16 mma.sync.
// CTA 128x128 (256 threads), warp grid 2M x 4N (warp tile 64x32),
// K-chunk 64, 3-stage cp.async, 2 CTAs/SM (launch_bounds(256,2)).
// Grids are 256 CTAs = exactly one wave at 2 CTAs/SM.
// MODE 0: out fp16, (B,L,C), bias by n      [Q, K heads]
// MODE 1: out fp16, (B,C,L), bias by m      [V heads]
// MODE 2: out fp32, (B,C,L), bias by m      [final output]
// ---------------------------------------------------------------------------
#define GM_A 0
#define GM_B 16384
#define GM_STAGE 32768
#define GM_SMEM (3*GM_STAGE)

template<int MODE>
__global__ __launch_bounds__(256, 2) void gemm_mma(
    const __half* __restrict__ A, const __half* __restrict__ B,
    const float* __restrict__ bias,
    __half* __restrict__ Oh, float* __restrict__ Of)
{
    extern __shared__ __align__(128) char sm[];
    const uint32_t sb = smem_u32(sm);
    const int tid = threadIdx.x, lane = tid & 31, wid = tid >> 5;
    const int warpM = wid >> 2, warpN = wid & 3;
    const int m0 = blockIdx.x * 128, n0 = blockIdx.y * 128;

    auto load_stage = [&](int s, int cch) {
        const int c0 = cch * 64;
        const uint32_t base = sb + s * GM_STAGE;
#pragma unroll
        for (int p = 0; p < 4; p++) {        // A: 128 rows x 8 quads
            int u = p * 256 + tid;
            int row = u >> 3, quad = u & 7;
            uint32_t so = (uint32_t)(row * 128 + ((quad ^ (row & 7)) << 4));
            CPA16(base + GM_A + so, A + (size_t)(m0 + row) * CC + c0 + quad * 8);
        }
#pragma unroll
        for (int p = 0; p < 4; p++) {        // B: 128 rows x 8 quads
            int u = p * 256 + tid;
            int row = u >> 3, quad = u & 7;
            uint32_t so = (uint32_t)(row * 128 + ((quad ^ (row & 7)) << 4));
            CPA16(base + GM_B + so, B + (size_t)(n0 + row) * CC + c0 + quad * 8);
        }
    };

    load_stage(0, 0); CPC();
    load_stage(1, 1); CPC();
    load_stage(2, 2); CPC();
    CPW2();
    __syncthreads();

    float C[4][4][4];
#pragma unroll
    for (int mf = 0; mf < 4; mf++)
#pragma unroll
        for (int nf = 0; nf < 4; nf++)
#pragma unroll
            for (int r = 0; r < 4; r++) C[mf][nf][r] = 0.f;

    const int arow = warpM * 64 + (lane & 15);
    const int aqb  = lane >> 4;
    const int brow = warpN * 32 + (lane & 7) + ((lane & 16) >> 1);
    const int bqb  = (lane >> 3) & 1;

    for (int cch = 0; cch < 8; cch++) {
        const int s = cch % 3;
        const uint32_t Ab = sb + s * GM_STAGE + GM_A;
        const uint32_t Bb = sb + s * GM_STAGE + GM_B;
#pragma unroll
        for (int ks = 0; ks < 4; ks++) {
            uint32_t af[4][4];
#pragma unroll
            for (int mf = 0; mf < 4; mf++) {
                int row = arow + mf * 16;
                int quad = 2 * ks + aqb;
                uint32_t off = (uint32_t)(row * 128 + ((quad ^ (row & 7)) << 4));
                LDSM4(af[mf], Ab + off);
            }
            uint32_t bf[4][2];
#pragma unroll
            for (int g = 0; g < 2; g++) {
                int row = brow + g * 16;
                int quad = 2 * ks + bqb;
                uint32_t off = (uint32_t)(row * 128 + ((quad ^ (row & 7)) << 4));
                uint32_t t0[4];
                LDSM4(t0, Bb + off);
                bf[2*g][0] = t0[0]; bf[2*g][1] = t0[1];
                bf[2*g+1][0] = t0[2]; bf[2*g+1][1] = t0[3];
            }
#pragma unroll
            for (int mf = 0; mf < 4; mf++)
#pragma unroll
                for (int nf = 0; nf < 4; nf++)
                    mma_f16(C[mf][nf], af[mf], bf[nf]);
        }
        __syncthreads();
        if (cch + 3 < 8) load_stage(s, cch + 3);
        CPC();
        CPW2();
        __syncthreads();
    }
    CPWALL();

    // epilogue
    const int mbase = m0 + warpM * 64 + (lane >> 2);
    const int nbase = n0 + warpN * 32 + 2 * (lane & 3);
#pragma unroll
    for (int mf = 0; mf < 4; mf++) {
#pragma unroll
        for (int nf = 0; nf < 4; nf++) {
            int mrow = mbase + mf * 16;
            int n = nbase + nf * 8;
            if (MODE == 0) {
                float b0 = __ldg(bias + n), b1 = __ldg(bias + n + 1);
                *(uint32_t*)(Oh + (size_t)mrow * CC + n) =
                    packh2(C[mf][nf][0] + b0, C[mf][nf][1] + b1);
                *(uint32_t*)(Oh + (size_t)(mrow + 8) * CC + n) =
                    packh2(C[mf][nf][2] + b0, C[mf][nf][3] + b1);
            } else {
                float bva = __ldg(bias + mrow), bvb = __ldg(bias + mrow + 8);
                int bb = n >> 11, lpos = n & 2047;
                size_t ob0 = ((size_t)(bb * CC + mrow)) * LL + lpos;
                size_t ob1 = ((size_t)(bb * CC + mrow + 8)) * LL + lpos;
                if (MODE == 1) {
                    *(uint32_t*)(Oh + ob0) = packh2(C[mf][nf][0] + bva, C[mf][nf][1] + bva);
                    *(uint32_t*)(Oh + ob1) = packh2(C[mf][nf][2] + bvb, C[mf][nf][3] + bvb);
                } else {
                    *(float2*)(Of + ob0) = make_float2(C[mf][nf][0] + bva, C[mf][nf][1] + bva);
                    *(float2*)(Of + ob1) = make_float2(C[mf][nf][2] + bvb, C[mf][nf][3] + bvb);
                }
            }
        }
    }
}

// ---------------------------------------------------------------------------
// Flash attention, fp16 mma.sync. CTA = 64 q x (head, batch), 256 threads,
// warp grid 4(M: 16 q each) x 2(N: 64 kpos each). KV blocks of 128, 3-stage.
// 2 CTAs per SM (launch_bounds(256,2)) so barriers don't idle the SM.
// ---------------------------------------------------------------------------
#define AT_Q 0
#define AT_QSZ 8192
#define AT_STRIDE 33280
#define AT_ST(s) (AT_QSZ + (s)*AT_STRIDE)
#define AT_K 0
#define AT_V 16384
#define AT_MSK 32768
#define AT_RED AT_QSZ                    // fp32 [4 warpM][16][72] = 18432 B (reuses stages)
#define AT_LSUM (AT_RED + 18432)         // fp32 [64][2]
#define AT_SMEM (AT_QSZ + 3*AT_STRIDE)   // 108032

__global__ __launch_bounds__(256, 2) void attn_mma(
    const float* __restrict__ mask,
    const __half* __restrict__ Qg, const __half* __restrict__ Kg,
    const __half* __restrict__ Vg,
    __half* __restrict__ Cg)
{
    extern __shared__ __align__(128) char sm[];
    const uint32_t sb = smem_u32(sm);
    const int tid = threadIdx.x, lane = tid & 31, wid = tid >> 5;
    const int warpM = wid >> 1, warpN = wid & 1;
    const int q0 = blockIdx.x * 64, h = blockIdx.y, b = blockIdx.z;
    const float scale = 0.125f;  // 1/sqrt(64)

    // load Q tile (plain stores), 64 rows x 64 half, swizzled 128B rows
#pragma unroll
    for (int p = 0; p < 2; p++) {
        int u = p * 256 + tid;
        int row = u >> 3, quad = u & 7;
        uint32_t so = (uint32_t)(row * 128 + ((quad ^ (row & 7)) << 4));
        size_t g = ((size_t)(b * LL + q0 + row)) * CC + h * DH + quad * 8;
        *(uint4*)(sm + AT_Q + so) = *(const uint4*)(Qg + g);
    }

    auto load_stage = [&](int s, int kb) {
        const int k0 = kb * 128;
        const uint32_t base = sb + AT_ST(s);
#pragma unroll
        for (int p = 0; p < 4; p++) {        // K: 128 rows x 8 quads
            int u = p * 256 + tid;
            int row = u >> 3, quad = u & 7;
            uint32_t so = (uint32_t)(row * 128 + ((quad ^ (row & 7)) << 4));
            CPA16(base + AT_K + so, Kg + ((size_t)(b * LL + k0 + row)) * CC + h * DH + quad * 8);
        }
#pragma unroll
        for (int p = 0; p < 4; p++) {        // V: 64 d-rows x 16 quads (256B rows)
            int u = p * 256 + tid;
            int row = u >> 4, quad = u & 15;
            uint32_t so = (uint32_t)(row * 256 + ((quad ^ (row & 7)) << 4));
            CPA16(base + AT_V + so, Vg + ((size_t)(b * CC + h * DH + row)) * LL + k0 + quad * 8);
        }
        if (tid < 128)
            ((float*)(sm + AT_ST(s) + AT_MSK))[tid] = mask[(size_t)b * LL + k0 + tid];
    };

    load_stage(0, 0); CPC();
    load_stage(1, 1); CPC();
    load_stage(2, 2); CPC();
    CPW2();
    __syncthreads();

    float O[8][4];
#pragma unroll
    for (int nf = 0; nf < 8; nf++)
#pragma unroll
        for (int r = 0; r < 4; r++) O[nf][r] = 0.f;
    float ls[2] = {0.f, 0.f};

    const int arow = warpM * 16 + (lane & 15);
    const int aqb  = lane >> 4;
    const int brow = warpN * 64 + (lane & 7) + ((lane & 16) >> 1);   // K rows
    const int vrow = (lane & 7) + ((lane & 16) >> 1);                // V rows (d)
    const int bqb  = (lane >> 3) & 1;

    for (int kb = 0; kb < 16; kb++) {
        const int s = kb % 3;
        const uint32_t Kb = sb + AT_ST(s) + AT_K;
        const uint32_t Vb = sb + AT_ST(s) + AT_V;
        const float* msk = (const float*)(sm + AT_ST(s) + AT_MSK);

        // ---- S = Q K^T (warp: 16 q x 64 kpos) ----
        float S[8][4];
#pragma unroll
        for (int nf = 0; nf < 8; nf++)
#pragma unroll
            for (int r = 0; r < 4; r++) S[nf][r] = 0.f;

#pragma unroll
        for (int ks = 0; ks < 4; ks++) {
            uint32_t qf[4];
            {
                int quad = 2 * ks + aqb;
                uint32_t off = (uint32_t)(arow * 128 + ((quad ^ (arow & 7)) << 4));
                LDSM4(qf, sb + AT_Q + off);
            }
            uint32_t kf[8][2];
#pragma unroll
            for (int g = 0; g < 4; g++) {
                int row = brow + g * 16;
                int quad = 2 * ks + bqb;
                uint32_t off = (uint32_t)(row * 128 + ((quad ^ (row & 7)) << 4));
                uint32_t t0[4];
                LDSM4(t0, Kb + off);
                kf[2*g][0] = t0[0]; kf[2*g][1] = t0[1];
                kf[2*g+1][0] = t0[2]; kf[2*g+1][1] = t0[3];
            }
#pragma unroll
            for (int nf = 0; nf < 8; nf++)
                mma_f16(S[nf], qf, kf[nf]);
        }

        // ---- softmax: mask + exp; pack P fp16 into A-fragment regs ----
        uint32_t ph[4][4];
#pragma unroll
        for (int nf = 0; nf < 8; nf++) {
            int ki = warpN * 64 + nf * 8 + 2 * (lane & 3);
            float mv0 = msk[ki], mv1 = msk[ki + 1];
            int ks2 = nf >> 1, half = nf & 1;
            float e00 = (mv0 > 0.5f) ? __expf(S[nf][0] * scale) : 0.f;
            float e01 = (mv1 > 0.5f) ? __expf(S[nf][1] * scale) : 0.f;
            float e10 = (mv0 > 0.5f) ? __expf(S[nf][2] * scale) : 0.f;
            float e11 = (mv1 > 0.5f) ? __expf(S[nf][3] * scale) : 0.f;
            ls[0] += e00 + e01;
            ls[1] += e10 + e11;
            ph[ks2][2 * half + 0] = packh2(e00, e01);
            ph[ks2][2 * half + 1] = packh2(e10, e11);
        }

        // ---- O += P V^T (warp: 16 q x 64 d, K-dim = its 64 kpos) ----
#pragma unroll
        for (int ks = 0; ks < 4; ks++) {
            uint32_t vf[8][2];
#pragma unroll
            for (int g = 0; g < 4; g++) {
                int row = vrow + g * 16;
                int quad = warpN * 8 + 2 * ks + bqb;
                uint32_t off = (uint32_t)(row * 256 + ((quad ^ (row & 7)) << 4));
                uint32_t t0[4];
                LDSM4(t0, Vb + off);
                vf[2*g][0] = t0[0]; vf[2*g][1] = t0[1];
                vf[2*g+1][0] = t0[2]; vf[2*g+1][1] = t0[3];
            }
#pragma unroll
            for (int nf = 0; nf < 8; nf++)
                mma_f16(O[nf], ph[ks], vf[nf]);
        }

        __syncthreads();
        if (kb + 3 < 16) load_stage(s, kb + 3);
        CPC();
        CPW2();
        __syncthreads();
    }
    CPWALL();

    // ---- lsum partials: reduce over lane&3, write [q][warpN] ----
    float* lsum_sm = (float*)(sm + AT_LSUM);
#pragma unroll
    for (int r = 0; r < 2; r++) {
        float v = ls[r];
        v += __shfl_xor_sync(0xffffffffu, v, 1);
        v += __shfl_xor_sync(0xffffffffu, v, 2);
        if ((lane & 3) == 0)
            lsum_sm[(warpM * 16 + (lane >> 2) + r * 8) * 2 + warpN] = v;
    }
    __syncthreads();

    // ---- O cross-warp reduce (warpN 1 -> smem, warpN 0 adds + writes) ----
    float* red = (float*)(sm + AT_RED) + warpM * (16 * 72);
    if (warpN == 1) {
#pragma unroll
        for (int nf = 0; nf < 8; nf++) {
            int lr = lane >> 2;
            int n = nf * 8 + 2 * (lane & 3);
            red[lr * 72 + n] = O[nf][0];
            red[lr * 72 + n + 1] = O[nf][1];
            red[(lr + 8) * 72 + n] = O[nf][2];
            red[(lr + 8) * 72 + n + 1] = O[nf][3];
        }
    }
    __syncthreads();
    if (warpN == 0) {
        int lr0 = lane >> 2;
        int lr1 = lr0 + 8;
        int q0r = warpM * 16 + lr0, q1r = warpM * 16 + lr1;
        float t0 = lsum_sm[q0r * 2] + lsum_sm[q0r * 2 + 1];
        float t1 = lsum_sm[q1r * 2] + lsum_sm[q1r * 2 + 1];
        float inv0 = (t0 > 0.f) ? 1.f / t0 : 0.f;
        float inv1 = (t1 > 0.f) ? 1.f / t1 : 0.f;
#pragma unroll
        for (int nf = 0; nf < 8; nf++) {
            int n = nf * 8 + 2 * (lane & 3);
            float f00 = (O[nf][0] + red[lr0 * 72 + n]) * inv0;
            float f01 = (O[nf][1] + red[lr0 * 72 + n + 1]) * inv0;
            float f10 = (O[nf][2] + red[lr1 * 72 + n]) * inv1;
            float f11 = (O[nf][3] + red[lr1 * 72 + n + 1]) * inv1;
            size_t g0 = ((size_t)(b * LL + q0 + q0r)) * CC + h * DH + n;
            size_t g1 = ((size_t)(b * LL + q0 + q1r)) * CC + h * DH + n;
            *(uint32_t*)(Cg + g0) = packh2(f00, f01);
            *(uint32_t*)(Cg + g1) = packh2(f10, f11);
        }
    }
}

// ---------------------------------------------------------------------------
extern "C" void kernel_launch(void* const* d_in, const int* in_sizes, int n_in,
                              void* d_out, int out_size)
{
    const float* q    = (const float*)d_in[0];
    const float* k    = (const float*)d_in[1];
    const float* v    = (const float*)d_in[2];
    const float* mask = (const float*)d_in[3];
    const float* Wq   = (const float*)d_in[4];
    const float* bq   = (const float*)d_in[5];
    const float* Wk   = (const float*)d_in[6];
    const float* bk   = (const float*)d_in[7];
    const float* Wv   = (const float*)d_in[8];
    const float* bv   = (const float*)d_in[9];
    const float* Wout = (const float*)d_in[10];
    const float* bout = (const float*)d_in[11];
    float* out = (float*)d_out;

    __half *xq, *xk, *xv, *wq, *wk, *wv, *wo, *qhH, *khH, *vhH, *ct;
    cudaGetSymbolAddress((void**)&xq, g_xq);
    cudaGetSymbolAddress((void**)&xk, g_xk);
    cudaGetSymbolAddress((void**)&xv, g_xv);
    cudaGetSymbolAddress((void**)&wq, g_wq);
    cudaGetSymbolAddress((void**)&wk, g_wk);
    cudaGetSymbolAddress((void**)&wv, g_wv);
    cudaGetSymbolAddress((void**)&wo, g_wo);
    cudaGetSymbolAddress((void**)&qhH, g_qhH);
    cudaGetSymbolAddress((void**)&khH, g_khH);
    cudaGetSymbolAddress((void**)&vhH, g_vhH);
    cudaGetSymbolAddress((void**)&ct, g_ct);

    cudaFuncSetAttribute(gemm_mma<0>, cudaFuncAttributeMaxDynamicSharedMemorySize, GM_SMEM);
    cudaFuncSetAttribute(gemm_mma<1>, cudaFuncAttributeMaxDynamicSharedMemorySize, GM_SMEM);
    cudaFuncSetAttribute(gemm_mma<2>, cudaFuncAttributeMaxDynamicSharedMemorySize, GM_SMEM);
    cudaFuncSetAttribute(attn_mma, cudaFuncAttributeMaxDynamicSharedMemorySize, AT_SMEM);

    dim3 tgrid(LL / 32, CC / 32, BB * 3), tblk(32, 8);
    tconv_kernel<<<tgrid, tblk>>>(q, k, v, xq, xk, xv);

    wconv_kernel<<<4 * CC * CC / 256, 256>>>(Wq, Wk, Wv, Wout, wq, wk, wv, wo);

    // Q, K projections -> (B,L,C) fp16   (grid 64x4 = 256 CTAs = one wave @ 2/SM)
    dim3 gA(BL / 128, CC / 128);
    gemm_mma<0><<<gA, 256, GM_SMEM>>>(xq, wq, bq, qhH, nullptr);
    gemm_mma<0><<<gA, 256, GM_SMEM>>>(xk, wk, bk, khH, nullptr);
    // V projection (W as A) -> (B,C,L) fp16  (grid 4x64 = 256 CTAs)
    dim3 gB(CC / 128, BL / 128);
    gemm_mma<1><<<gB, 256, GM_SMEM>>>(wv, xv, bv, vhH, nullptr);

    dim3 agrid(LL / 64, HH, BB);
    attn_mma<<<agrid, 256, AT_SMEM>>>(mask, qhH, khH, vhH, ct);

    // Output projection (W as A) -> (B,C,L) fp32
    gemm_mma<2><<<gB, 256, GM_SMEM>>>(wo, ct, bout, nullptr, out);
}

// round 14
// speedup vs baseline: 1.1429x; 1.1429x over previous
#include <cuda_runtime.h>
#include <cuda_bf16.h>
#include <cuda_fp16.h>
#include <cstdint>
#include <cstddef>

#define BB 4
#define CC 512
#define LL 2048
#define HH 8
#define DH 64
#define BL (BB*LL)

// ---------------------------------------------------------------------------
// Scratch (all single fp16)
// ---------------------------------------------------------------------------
__device__ __half g_xq[BL*CC];     // (B,L,C) transposed inputs
__device__ __half g_xk[BL*CC];
__device__ __half g_xv[BL*CC];
__device__ __half g_wq[CC*CC];
__device__ __half g_wk[CC*CC];
__device__ __half g_wv[CC*CC];
__device__ __half g_wo[CC*CC];
__device__ __half g_qhH[BL*CC];    // (B,L,C)
__device__ __half g_khH[BL*CC];    // (B,L,C)
__device__ __half g_vhH[BL*CC];    // (B,C,L)
__device__ __half g_ct[BL*CC];     // (B,L,C)

// ---------------------------------------------------------------------------
// Helpers
// ---------------------------------------------------------------------------
__device__ __forceinline__ uint32_t smem_u32(const void* p) {
    uint32_t a;
    asm("{ .reg .u64 t; cvta.to.shared.u64 t, %1; cvt.u32.u64 %0, t; }" : "=r"(a) : "l"(p));
    return a;
}

#define LDSM4(R, a) \
    asm volatile("ldmatrix.sync.aligned.m8n8.x4.shared.b16 {%0,%1,%2,%3}, [%4];" \
        : "=r"((R)[0]), "=r"((R)[1]), "=r"((R)[2]), "=r"((R)[3]) : "r"(a))

#define CPA16(d, s) \
    asm volatile("cp.async.cg.shared.global [%0], [%1], 16;" :: "r"(d), "l"(s))
#define CPC()   asm volatile("cp.async.commit_group;" ::: "memory")
#define CPW1()  asm volatile("cp.async.wait_group 1;" ::: "memory")
#define CPW2()  asm volatile("cp.async.wait_group 2;" ::: "memory")
#define CPWALL() asm volatile("cp.async.wait_group 0;" ::: "memory")

__device__ __forceinline__ void mma_f16(float* c, const uint32_t* a, const uint32_t* b) {
    asm volatile("mma.sync.aligned.m16n8k16.row.col.f32.f16.f16.f32 "
        "{%0,%1,%2,%3}, {%4,%5,%6,%7}, {%8,%9}, {%0,%1,%2,%3};"
        : "+f"(c[0]), "+f"(c[1]), "+f"(c[2]), "+f"(c[3])
        : "r"(a[0]), "r"(a[1]), "r"(a[2]), "r"(a[3]), "r"(b[0]), "r"(b[1]));
}

__device__ __forceinline__ uint32_t packh2(float a, float b) {
    __half2 t = __floats2half2_rn(a, b);
    return *reinterpret_cast<uint32_t*>(&t);
}

// pack(lo=f0, hi=f1) then 2^x on both halves
__device__ __forceinline__ uint32_t exp2h2(float f0, float f1) {
    uint32_t r;
    asm("{ .reg .b32 t; cvt.rn.f16x2.f32 t, %1, %2; ex2.approx.f16x2 %0, t; }"
        : "=r"(r) : "f"(f1), "f"(f0));
    return r;
}

// ---------------------------------------------------------------------------
// Pre-pass: transpose (B,C,L) fp32 -> (B*L, C) fp16, all 3 tensors in one grid
// ---------------------------------------------------------------------------
__global__ __launch_bounds__(256) void tconv_kernel(
    const float* __restrict__ Xq, const float* __restrict__ Xk, const float* __restrict__ Xv,
    __half* __restrict__ Tq, __half* __restrict__ Tk, __half* __restrict__ Tv)
{
    __shared__ float t[32][33];
    const int zz = blockIdx.z;
    const int which = zz >> 2, b = zz & 3;
    const float* X = (which == 0) ? Xq : (which == 1) ? Xk : Xv;
    __half* T = (which == 0) ? Tq : (which == 1) ? Tk : Tv;
    const int l0 = blockIdx.x * 32, c0 = blockIdx.y * 32;
    const int tx = threadIdx.x, ty = threadIdx.y;
    const float* Xb = X + ((size_t)b * CC + c0) * LL + l0;
#pragma unroll
    for (int i = 0; i < 4; i++)
        t[ty + i * 8][tx] = Xb[(size_t)(ty + i * 8) * LL + tx];
    __syncthreads();
    const size_t ob = ((size_t)b * LL + l0) * CC + c0;
#pragma unroll
    for (int i = 0; i < 4; i++) {
        int lr = ty + i * 8;
        T[ob + (size_t)lr * CC + tx] = __float2half_rn(t[tx][lr]);
    }
}

// All 4 weight matrices in one launch
__global__ __launch_bounds__(256) void wconv_kernel(
    const float* __restrict__ W0, const float* __restrict__ W1,
    const float* __restrict__ W2, const float* __restrict__ W3,
    __half* __restrict__ O0, __half* __restrict__ O1,
    __half* __restrict__ O2, __half* __restrict__ O3)
{
    int gi = blockIdx.x * 256 + threadIdx.x;
    int which = gi >> 18;           // CC*CC = 262144 = 2^18
    int i = gi & 0x3FFFF;
    const float* W = (which == 0) ? W0 : (which == 1) ? W1 : (which == 2) ? W2 : W3;
    __half* O = (which == 0) ? O0 : (which == 1) ? O1 : (which == 2) ? O2 : O3;
    O[i] = __float2half_rn(W[i]);
}

// ---------------------------------------------------------------------------
// GEMM (R11 proven config): D[m,n] = sum_k A[m,k]*B[n,k] (+bias), fp16 mma.
// CTA 256x128 (512 threads), warp grid 4M x 4N (warp tile 64x32),
// K-chunk 64, 2-stage cp.async. All grids are exactly 128 CTAs (one wave).
// ---------------------------------------------------------------------------
#define GM_A 0
#define GM_B 32768
#define GM_STAGE 49152
#define GM_SMEM (2*GM_STAGE)

template<int MODE>
__global__ __launch_bounds__(512, 1) void gemm_mma(
    const __half* __restrict__ A, const __half* __restrict__ B,
    const float* __restrict__ bias,
    __half* __restrict__ Oh, float* __restrict__ Of)
{
    extern __shared__ __align__(128) char sm[];
    const uint32_t sb = smem_u32(sm);
    const int tid = threadIdx.x, lane = tid & 31, wid = tid >> 5;
    const int warpM = wid >> 2, warpN = wid & 3;
    const int m0 = blockIdx.x * 256, n0 = blockIdx.y * 128;

    auto load_stage = [&](int s, int cch) {
        const int c0 = cch * 64;
        const uint32_t base = sb + s * GM_STAGE;
#pragma unroll
        for (int p = 0; p < 4; p++) {        // A: 256 rows x 8 quads
            int u = p * 512 + tid;
            int row = u >> 3, quad = u & 7;
            uint32_t so = (uint32_t)(row * 128 + ((quad ^ (row & 7)) << 4));
            CPA16(base + GM_A + so, A + (size_t)(m0 + row) * CC + c0 + quad * 8);
        }
#pragma unroll
        for (int p = 0; p < 2; p++) {        // B: 128 rows x 8 quads
            int u = p * 512 + tid;
            int row = u >> 3, quad = u & 7;
            uint32_t so = (uint32_t)(row * 128 + ((quad ^ (row & 7)) << 4));
            CPA16(base + GM_B + so, B + (size_t)(n0 + row) * CC + c0 + quad * 8);
        }
    };

    load_stage(0, 0); CPC();

    float C[4][4][4];
#pragma unroll
    for (int mf = 0; mf < 4; mf++)
#pragma unroll
        for (int nf = 0; nf < 4; nf++)
#pragma unroll
            for (int r = 0; r < 4; r++) C[mf][nf][r] = 0.f;

    const int arow = warpM * 64 + (lane & 15);
    const int aqb  = lane >> 4;
    const int brow = warpN * 32 + (lane & 7) + ((lane & 16) >> 1);
    const int bqb  = (lane >> 3) & 1;

    for (int cch = 0; cch < 8; cch++) {
        const int s = cch & 1;
        if (cch + 1 < 8) { load_stage(s ^ 1, cch + 1); CPC(); CPW1(); }
        else             { CPWALL(); }
        __syncthreads();

        const uint32_t Ab = sb + s * GM_STAGE + GM_A;
        const uint32_t Bb = sb + s * GM_STAGE + GM_B;
#pragma unroll
        for (int ks = 0; ks < 4; ks++) {
            uint32_t af[4][4];
#pragma unroll
            for (int mf = 0; mf < 4; mf++) {
                int row = arow + mf * 16;
                int quad = 2 * ks + aqb;
                uint32_t off = (uint32_t)(row * 128 + ((quad ^ (row & 7)) << 4));
                LDSM4(af[mf], Ab + off);
            }
            uint32_t bf[4][2];
#pragma unroll
            for (int g = 0; g < 2; g++) {
                int row = brow + g * 16;
                int quad = 2 * ks + bqb;
                uint32_t off = (uint32_t)(row * 128 + ((quad ^ (row & 7)) << 4));
                uint32_t t0[4];
                LDSM4(t0, Bb + off);
                bf[2*g][0] = t0[0]; bf[2*g][1] = t0[1];
                bf[2*g+1][0] = t0[2]; bf[2*g+1][1] = t0[3];
            }
#pragma unroll
            for (int mf = 0; mf < 4; mf++)
#pragma unroll
                for (int nf = 0; nf < 4; nf++)
                    mma_f16(C[mf][nf], af[mf], bf[nf]);
        }
        __syncthreads();
    }

    // epilogue
    const int mbase = m0 + warpM * 64 + (lane >> 2);
    const int nbase = n0 + warpN * 32 + 2 * (lane & 3);
#pragma unroll
    for (int mf = 0; mf < 4; mf++) {
#pragma unroll
        for (int nf = 0; nf < 4; nf++) {
            int mrow = mbase + mf * 16;
            int n = nbase + nf * 8;
            if (MODE == 0) {
                float b0 = __ldg(bias + n), b1 = __ldg(bias + n + 1);
                *(uint32_t*)(Oh + (size_t)mrow * CC + n) =
                    packh2(C[mf][nf][0] + b0, C[mf][nf][1] + b1);
                *(uint32_t*)(Oh + (size_t)(mrow + 8) * CC + n) =
                    packh2(C[mf][nf][2] + b0, C[mf][nf][3] + b1);
            } else {
                float bva = __ldg(bias + mrow), bvb = __ldg(bias + mrow + 8);
                int bb = n >> 11, lpos = n & 2047;
                size_t ob0 = ((size_t)(bb * CC + mrow)) * LL + lpos;
                size_t ob1 = ((size_t)(bb * CC + mrow + 8)) * LL + lpos;
                if (MODE == 1) {
                    *(uint32_t*)(Oh + ob0) = packh2(C[mf][nf][0] + bva, C[mf][nf][1] + bva);
                    *(uint32_t*)(Oh + ob1) = packh2(C[mf][nf][2] + bvb, C[mf][nf][3] + bvb);
                } else {
                    *(float2*)(Of + ob0) = make_float2(C[mf][nf][0] + bva, C[mf][nf][1] + bva);
                    *(float2*)(Of + ob1) = make_float2(C[mf][nf][2] + bvb, C[mf][nf][3] + bvb);
                }
            }
        }
    }
}

// ---------------------------------------------------------------------------
// Flash attention, fp16 mma.sync. CTA = 64 q x (head, batch), 256 threads,
// warp grid 4(M: 16 q each) x 2(N: 64 kpos each). KV blocks of 128, 3-stage,
// 2 CTAs/SM. Softmax: additive mask + ex2.approx.f16x2; row-sums via an
// extra MMA against a ones B-fragment (common-mode fp16 error cancels).
// ---------------------------------------------------------------------------
#define AT_Q 0
#define AT_QSZ 8192
#define AT_STRIDE 33280
#define AT_ST(s) (AT_QSZ + (s)*AT_STRIDE)
#define AT_K 0
#define AT_V 16384
#define AT_MSK 32768
#define AT_RED AT_QSZ                    // fp32 [4 warpM][16][72] = 18432 B (reuses stages)
#define AT_LSUM (AT_RED + 18432)         // fp32 [64][2]
#define AT_SMEM (AT_QSZ + 3*AT_STRIDE)   // 108032

__global__ __launch_bounds__(256, 2) void attn_mma(
    const float* __restrict__ mask,
    const __half* __restrict__ Qg, const __half* __restrict__ Kg,
    const __half* __restrict__ Vg,
    __half* __restrict__ Cg)
{
    extern __shared__ __align__(128) char sm[];
    const uint32_t sb = smem_u32(sm);
    const int tid = threadIdx.x, lane = tid & 31, wid = tid >> 5;
    const int warpM = wid >> 1, warpN = wid & 1;
    const int q0 = blockIdx.x * 64, h = blockIdx.y, b = blockIdx.z;
    const float k2e = 0.1803368801f;   // (1/sqrt(64)) * log2(e)

    // load Q tile (plain stores), 64 rows x 64 half, swizzled 128B rows
#pragma unroll
    for (int p = 0; p < 2; p++) {
        int u = p * 256 + tid;
        int row = u >> 3, quad = u & 7;
        uint32_t so = (uint32_t)(row * 128 + ((quad ^ (row & 7)) << 4));
        size_t g = ((size_t)(b * LL + q0 + row)) * CC + h * DH + quad * 8;
        *(uint4*)(sm + AT_Q + so) = *(const uint4*)(Qg + g);
    }

    auto load_stage = [&](int s, int kb) {
        const int k0 = kb * 128;
        const uint32_t base = sb + AT_ST(s);
#pragma unroll
        for (int p = 0; p < 4; p++) {        // K: 128 rows x 8 quads
            int u = p * 256 + tid;
            int row = u >> 3, quad = u & 7;
            uint32_t so = (uint32_t)(row * 128 + ((quad ^ (row & 7)) << 4));
            CPA16(base + AT_K + so, Kg + ((size_t)(b * LL + k0 + row)) * CC + h * DH + quad * 8);
        }
#pragma unroll
        for (int p = 0; p < 4; p++) {        // V: 64 d-rows x 16 quads (256B rows)
            int u = p * 256 + tid;
            int row = u >> 4, quad = u & 15;
            uint32_t so = (uint32_t)(row * 256 + ((quad ^ (row & 7)) << 4));
            CPA16(base + AT_V + so, Vg + ((size_t)(b * CC + h * DH + row)) * LL + k0 + quad * 8);
        }
        if (tid < 128) {
            float mv = mask[(size_t)b * LL + k0 + tid];
            // additive mask in log2 domain: 0 keeps, -30000 -> 2^-30000 = 0
            ((float*)(sm + AT_ST(s) + AT_MSK))[tid] = (mv > 0.5f) ? 0.f : -30000.f;
        }
    };

    load_stage(0, 0); CPC();
    load_stage(1, 1); CPC();
    load_stage(2, 2); CPC();
    CPW2();
    __syncthreads();

    float O[8][4];
#pragma unroll
    for (int nf = 0; nf < 8; nf++)
#pragma unroll
        for (int r = 0; r < 4; r++) O[nf][r] = 0.f;
    float LS[4] = {0.f, 0.f, 0.f, 0.f};
    const uint32_t ones2 = 0x3C003C00u;             // half2(1.0, 1.0)
    const uint32_t bones[2] = {ones2, ones2};

    const int arow = warpM * 16 + (lane & 15);
    const int aqb  = lane >> 4;
    const int brow = warpN * 64 + (lane & 7) + ((lane & 16) >> 1);   // K rows
    const int vrow = (lane & 7) + ((lane & 16) >> 1);                // V rows (d)
    const int bqb  = (lane >> 3) & 1;

    for (int kb = 0; kb < 16; kb++) {
        const int s = kb % 3;
        const uint32_t Kb = sb + AT_ST(s) + AT_K;
        const uint32_t Vb = sb + AT_ST(s) + AT_V;
        const float* msk = (const float*)(sm + AT_ST(s) + AT_MSK);

        // ---- S = Q K^T (warp: 16 q x 64 kpos) ----
        float S[8][4];
#pragma unroll
        for (int nf = 0; nf < 8; nf++)
#pragma unroll
            for (int r = 0; r < 4; r++) S[nf][r] = 0.f;

#pragma unroll
        for (int ks = 0; ks < 4; ks++) {
            uint32_t qf[4];
            {
                int quad = 2 * ks + aqb;
                uint32_t off = (uint32_t)(arow * 128 + ((quad ^ (arow & 7)) << 4));
                LDSM4(qf, sb + AT_Q + off);
            }
            uint32_t kf[8][2];
#pragma unroll
            for (int g = 0; g < 4; g++) {
                int row = brow + g * 16;
                int quad = 2 * ks + bqb;
                uint32_t off = (uint32_t)(row * 128 + ((quad ^ (row & 7)) << 4));
                uint32_t t0[4];
                LDSM4(t0, Kb + off);
                kf[2*g][0] = t0[0]; kf[2*g][1] = t0[1];
                kf[2*g+1][0] = t0[2]; kf[2*g+1][1] = t0[3];
            }
#pragma unroll
            for (int nf = 0; nf < 8; nf++)
                mma_f16(S[nf], qf, kf[nf]);
        }

        // ---- softmax: P = 2^(S*k2e + madd), packed fp16x2 A-fragments ----
        uint32_t ph[4][4];
#pragma unroll
        for (int nf = 0; nf < 8; nf++) {
            int ki = warpN * 64 + nf * 8 + 2 * (lane & 3);
            float m0 = msk[ki], m1 = msk[ki + 1];
            int ks2 = nf >> 1, half = nf & 1;
            float f0 = fmaf(S[nf][0], k2e, m0);
            float f1 = fmaf(S[nf][1], k2e, m1);
            float f2 = fmaf(S[nf][2], k2e, m0);
            float f3 = fmaf(S[nf][3], k2e, m1);
            ph[ks2][2 * half + 0] = exp2h2(f0, f1);
            ph[ks2][2 * half + 1] = exp2h2(f2, f3);
        }

        // ---- O += P V^T, and LS += P * ones (row sums) ----
#pragma unroll
        for (int ks = 0; ks < 4; ks++) {
            uint32_t vf[8][2];
#pragma unroll
            for (int g = 0; g < 4; g++) {
                int row = vrow + g * 16;
                int quad = warpN * 8 + 2 * ks + bqb;
                uint32_t off = (uint32_t)(row * 256 + ((quad ^ (row & 7)) << 4));
                uint32_t t0[4];
                LDSM4(t0, Vb + off);
                vf[2*g][0] = t0[0]; vf[2*g][1] = t0[1];
                vf[2*g+1][0] = t0[2]; vf[2*g+1][1] = t0[3];
            }
#pragma unroll
            for (int nf = 0; nf < 8; nf++)
                mma_f16(O[nf], ph[ks], vf[nf]);
            mma_f16(LS, ph[ks], bones);
        }

        __syncthreads();
        if (kb + 3 < 16) load_stage(s, kb + 3);
        CPC();
        CPW2();
        __syncthreads();
    }
    CPWALL();

    // ---- lsum partials: LS[0] = rowsum(q), LS[2] = rowsum(q+8) ----
    float* lsum_sm = (float*)(sm + AT_LSUM);
    if ((lane & 3) == 0) {
        lsum_sm[(warpM * 16 + (lane >> 2)) * 2 + warpN] = LS[0];
        lsum_sm[(warpM * 16 + (lane >> 2) + 8) * 2 + warpN] = LS[2];
    }
    __syncthreads();

    // ---- O cross-warp reduce (warpN 1 -> smem, warpN 0 adds + writes) ----
    float* red = (float*)(sm + AT_RED) + warpM * (16 * 72);
    if (warpN == 1) {
#pragma unroll
        for (int nf = 0; nf < 8; nf++) {
            int lr = lane >> 2;
            int n = nf * 8 + 2 * (lane & 3);
            red[lr * 72 + n] = O[nf][0];
            red[lr * 72 + n + 1] = O[nf][1];
            red[(lr + 8) * 72 + n] = O[nf][2];
            red[(lr + 8) * 72 + n + 1] = O[nf][3];
        }
    }
    __syncthreads();
    if (warpN == 0) {
        int lr0 = lane >> 2;
        int lr1 = lr0 + 8;
        int q0r = warpM * 16 + lr0, q1r = warpM * 16 + lr1;
        float t0 = lsum_sm[q0r * 2] + lsum_sm[q0r * 2 + 1];
        float t1 = lsum_sm[q1r * 2] + lsum_sm[q1r * 2 + 1];
        float inv0 = (t0 > 0.f) ? 1.f / t0 : 0.f;
        float inv1 = (t1 > 0.f) ? 1.f / t1 : 0.f;
#pragma unroll
        for (int nf = 0; nf < 8; nf++) {
            int n = nf * 8 + 2 * (lane & 3);
            float f00 = (O[nf][0] + red[lr0 * 72 + n]) * inv0;
            float f01 = (O[nf][1] + red[lr0 * 72 + n + 1]) * inv0;
            float f10 = (O[nf][2] + red[lr1 * 72 + n]) * inv1;
            float f11 = (O[nf][3] + red[lr1 * 72 + n + 1]) * inv1;
            size_t g0 = ((size_t)(b * LL + q0 + q0r)) * CC + h * DH + n;
            size_t g1 = ((size_t)(b * LL + q0 + q1r)) * CC + h * DH + n;
            *(uint32_t*)(Cg + g0) = packh2(f00, f01);
            *(uint32_t*)(Cg + g1) = packh2(f10, f11);
        }
    }
}

// ---------------------------------------------------------------------------
extern "C" void kernel_launch(void* const* d_in, const int* in_sizes, int n_in,
                              void* d_out, int out_size)
{
    const float* q    = (const float*)d_in[0];
    const float* k    = (const float*)d_in[1];
    const float* v    = (const float*)d_in[2];
    const float* mask = (const float*)d_in[3];
    const float* Wq   = (const float*)d_in[4];
    const float* bq   = (const float*)d_in[5];
    const float* Wk   = (const float*)d_in[6];
    const float* bk   = (const float*)d_in[7];
    const float* Wv   = (const float*)d_in[8];
    const float* bv   = (const float*)d_in[9];
    const float* Wout = (const float*)d_in[10];
    const float* bout = (const float*)d_in[11];
    float* out = (float*)d_out;

    __half *xq, *xk, *xv, *wq, *wk, *wv, *wo, *qhH, *khH, *vhH, *ct;
    cudaGetSymbolAddress((void**)&xq, g_xq);
    cudaGetSymbolAddress((void**)&xk, g_xk);
    cudaGetSymbolAddress((void**)&xv, g_xv);
    cudaGetSymbolAddress((void**)&wq, g_wq);
    cudaGetSymbolAddress((void**)&wk, g_wk);
    cudaGetSymbolAddress((void**)&wv, g_wv);
    cudaGetSymbolAddress((void**)&wo, g_wo);
    cudaGetSymbolAddress((void**)&qhH, g_qhH);
    cudaGetSymbolAddress((void**)&khH, g_khH);
    cudaGetSymbolAddress((void**)&vhH, g_vhH);
    cudaGetSymbolAddress((void**)&ct, g_ct);

    cudaFuncSetAttribute(gemm_mma<0>, cudaFuncAttributeMaxDynamicSharedMemorySize, GM_SMEM);
    cudaFuncSetAttribute(gemm_mma<1>, cudaFuncAttributeMaxDynamicSharedMemorySize, GM_SMEM);
    cudaFuncSetAttribute(gemm_mma<2>, cudaFuncAttributeMaxDynamicSharedMemorySize, GM_SMEM);
    cudaFuncSetAttribute(attn_mma, cudaFuncAttributeMaxDynamicSharedMemorySize, AT_SMEM);

    dim3 tgrid(LL / 32, CC / 32, BB * 3), tblk(32, 8);
    tconv_kernel<<<tgrid, tblk>>>(q, k, v, xq, xk, xv);

    wconv_kernel<<<4 * CC * CC / 256, 256>>>(Wq, Wk, Wv, Wout, wq, wk, wv, wo);

    // Q, K projections -> (B,L,C) fp16   (grid 32x4 = 128 CTAs, one wave)
    dim3 gA(BL / 256, CC / 128);
    gemm_mma<0><<<gA, 512, GM_SMEM>>>(xq, wq, bq, qhH, nullptr);
    gemm_mma<0><<<gA, 512, GM_SMEM>>>(xk, wk, bk, khH, nullptr);
    // V projection (W as A) -> (B,C,L) fp16  (grid 2x64 = 128 CTAs)
    dim3 gB(CC / 256, BL / 128);
    gemm_mma<1><<<gB, 512, GM_SMEM>>>(wv, xv, bv, vhH, nullptr);

    dim3 agrid(LL / 64, HH, BB);
    attn_mma<<<agrid, 256, AT_SMEM>>>(mask, qhH, khH, vhH, ct);

    // Output projection (W as A) -> (B,C,L) fp32
    gemm_mma<2><<<gB, 512, GM_SMEM>>>(wo, ct, bout, nullptr, out);
}